// round 9
// baseline (speedup 1.0000x reference)
#include <cuda_runtime.h>
#include <cuda_bf16.h>
#include <math_constants.h>
#include <cstdint>

#define NN 8192
#define L2E 1.4426950408889634f

__device__ float g_h[NN*64];
__device__ __nv_bfloat16 g_q[NN*64];   // pre-scaled by gate * 0.125 * log2(e)
__device__ __nv_bfloat16 g_k[NN*64];
__device__ __nv_bfloat16 g_mT[64*NN];  // transposed: [dim][node]
__device__ float g_emb[NN*64];
__device__ float g_s[NN];
__device__ float g_gate;
__device__ float g_sbc;                // stateful_bias * (1 - t0) * log2(e)

__device__ __forceinline__ float ex2f(float x) {
    float y; asm("ex2.approx.ftz.f32 %0, %1;" : "=f"(y) : "f"(x)); return y;
}
__device__ __forceinline__ uint32_t pkbf(float a, float b) {
    __nv_bfloat162 t = __floats2bfloat162_rn(a, b);
    return *reinterpret_cast<uint32_t*>(&t);
}
__device__ __forceinline__ void mma_bf16(float* c, const uint32_t* a, const uint32_t* b) {
    asm volatile("mma.sync.aligned.m16n8k16.row.col.f32.bf16.bf16.f32 "
                 "{%0,%1,%2,%3},{%4,%5,%6,%7},{%8,%9},{%0,%1,%2,%3};"
                 : "+f"(c[0]), "+f"(c[1]), "+f"(c[2]), "+f"(c[3])
                 : "r"(a[0]), "r"(a[1]), "r"(a[2]), "r"(a[3]), "r"(b[0]), "r"(b[1]));
}
#define CP16(d, s) asm volatile("cp.async.cg.shared.global [%0], [%1], 16;" :: "r"(d), "l"(s))
#define CPCOM()    asm volatile("cp.async.commit_group;" ::: "memory")
#define CPWAIT(n)  asm volatile("cp.async.wait_group %0;" :: "n"(n) : "memory")

// ---------------- Kernel 0: scalars ---------------------------------------------
__global__ void k_scalars(const float* __restrict__ trig, const float* __restrict__ wg,
                          const float* __restrict__ bg, const float* __restrict__ sbias) {
    int d = threadIdx.x;
    float t0 = trig[0], t1 = trig[1];
    float v = t0 * wg[d] + t1 * wg[64 + d] + bg[d];
    float sig = 1.0f / (1.0f + __expf(-v));
    #pragma unroll
    for (int o = 16; o > 0; o >>= 1) sig += __shfl_xor_sync(0xffffffffu, sig, o);
    __shared__ float ws[2];
    if ((d & 31) == 0) ws[d >> 5] = sig;
    __syncthreads();
    if (d == 0) {
        g_gate = (ws[0] + ws[1]) * (1.0f / 64.0f);
        g_sbc  = sbias[0] * (1.0f - t0) * L2E;
    }
}

// ---------------- Kernel 1: per-node MLP -> h(f32), q/k bf16, mT bf16 -----------
__global__ void __launch_bounds__(256) k_mlp(
    const float* __restrict__ nf, const float* __restrict__ trig,
    const float* __restrict__ w1, const float* __restrict__ b1,
    const float* __restrict__ w2, const float* __restrict__ b2,
    const float* __restrict__ wq, const float* __restrict__ bq,
    const float* __restrict__ wk, const float* __restrict__ bk,
    const float* __restrict__ wm, const float* __restrict__ bm) {
    __shared__ float h1[4][64];
    __shared__ float hh[4][64];
    __shared__ float stg[64][36];   // m staging for transpose: [dim][local node]
    int g = threadIdx.x >> 6, d = threadIdx.x & 63;
    float t0 = trig[0], t1 = trig[1];
    float qsc = g_gate * 0.125f * L2E;
    int i0 = blockIdx.x * 32;
    for (int it = 0; it < 8; ++it) {
        int ln = g * 8 + it;
        int i = i0 + ln;
        float x0 = nf[i*3+0], x1 = nf[i*3+1], x2 = nf[i*3+2];
        float a = b1[d] + x0*w1[d] + x1*w1[64+d] + x2*w1[128+d] + t0*w1[192+d] + t1*w1[256+d];
        h1[g][d] = fmaxf(a, 0.0f);
        __syncthreads();
        float s2 = b2[d];
        #pragma unroll 8
        for (int e = 0; e < 64; ++e) s2 += h1[g][e] * w2[e*64 + d];
        hh[g][d] = s2;
        g_h[i*64 + d] = s2;
        __syncthreads();
        float q = bq[d], k = bk[d], m = bm[d];
        #pragma unroll 8
        for (int e = 0; e < 64; ++e) {
            float he = hh[g][e];
            q += he * wq[e*64 + d];
            k += he * wk[e*64 + d];
            m += he * wm[e*64 + d];
        }
        g_q[i*64 + d] = __float2bfloat16(q * qsc);
        g_k[i*64 + d] = __float2bfloat16(k);
        stg[d][ln] = m;
        if (d == 0) g_s[i] = x2;
        __syncthreads();
    }
    // transposed write-out of m
    int dd = threadIdx.x >> 2, p = threadIdx.x & 3;
    float4 v0 = *(float4*)&stg[dd][p*8];
    float4 v1 = *(float4*)&stg[dd][p*8 + 4];
    uint32_t o[4] = {pkbf(v0.x, v0.y), pkbf(v0.z, v0.w), pkbf(v1.x, v1.y), pkbf(v1.z, v1.w)};
    *(uint4*)(g_mT + (size_t)dd*NN + i0 + p*8) = *(uint4*)o;
}

// ---------------- Kernel 2: flash attention, 512 threads, pipelined PV ----------
// 16 warps = 4x4 grid; warp tile 16x16; bf16 mma m16n8k16.
// K: 3 bufs, M: 4 bufs, P: 2 bufs (PV deferred one iteration).
#define KSTR 36
#define TILE_W (64*KSTR)          // 2304 words
#define OFF_K 0                   // 3 tiles
#define OFF_M (3*TILE_W)          // 4 tiles
#define OFF_Q (7*TILE_W)
#define OFF_P (8*TILE_W)          // 2 tiles
#define OFF_RED (10*TILE_W)       // 4x64 words
#define SMEM_WORDS (10*TILE_W + 256)

__global__ void __launch_bounds__(512) k_attn(const float* __restrict__ adj,
                                              const float* __restrict__ lng,
                                              const float* __restrict__ lnb) {
    extern __shared__ uint32_t smw[];
    const int t = threadIdx.x;
    const int warp = t >> 5, lane = t & 31;
    const int wr = warp >> 2, wc = warp & 3;
    const int qr = lane >> 2, four = lane & 3;
    const int r0 = blockIdx.x * 64;
    const int rowa = wr * 16 + qr;
    const uint32_t sbase = (uint32_t)__cvta_generic_to_shared(smw);
    const int cr = t >> 3, cco = t & 7;     // copy row / col (one 16B chunk each)

    auto cpK = [&](int tile, int buf) {
        uint32_t dk = sbase + (OFF_K + buf * TILE_W) * 4;
        CP16(dk + (cr * KSTR + cco * 4) * 4, g_k + (size_t)(tile * 64 + cr) * 64 + cco * 8);
    };
    auto cpM = [&](int tile, int buf) {
        uint32_t dm = sbase + (OFF_M + buf * TILE_W) * 4;
        CP16(dm + (cr * KSTR + cco * 4) * 4, g_mT + (size_t)cr * NN + tile * 64 + cco * 8);
    };
    // prologue: Q + tiles 0,1
    {
        uint32_t dq = sbase + OFF_Q * 4;
        CP16(dq + (cr * KSTR + cco * 4) * 4, g_q + (size_t)(r0 + cr) * 64 + cco * 8);
        cpK(0, 0); cpM(0, 0); CPCOM();
        cpK(1, 1); cpM(1, 1); CPCOM();
    }

    const float sbc = g_sbc;
    const float srb0 = g_s[r0 + rowa] * sbc;
    const float srb1 = g_s[r0 + rowa + 8] * sbc;
    const float* adjr0 = adj + (size_t)(r0 + rowa) * NN + wc * 16 + 2 * four;
    const float* adjr1 = adjr0 + (size_t)8 * NN;

    const uint32_t* Qw = smw + OFF_Q;
    float* redl = (float*)(smw + OFF_RED);

    float psum0 = 0.0f, psum1 = 0.0f;
    float acc[2][4];
    #pragma unroll
    for (int ni = 0; ni < 2; ++ni)
        #pragma unroll
        for (int e = 0; e < 4; ++e) acc[ni][e] = 0.0f;

    for (int ct = 0; ct < 128; ++ct) {
        const int c0 = ct * 64;
        float2 adjv[4], scv[2];
        #pragma unroll
        for (int ni = 0; ni < 2; ++ni) {
            scv[ni]      = *(const float2*)(g_s + c0 + wc * 16 + ni * 8 + 2 * four);
            adjv[ni*2+0] = __ldcs((const float2*)(adjr0 + c0 + ni * 8));
            adjv[ni*2+1] = __ldcs((const float2*)(adjr1 + c0 + ni * 8));
        }
        CPWAIT(1);
        __syncthreads();
        int nt = ct + 2; if (nt > 127) nt = 127;
        cpK(nt, (ct + 2) % 3); cpM(nt, (ct + 2) % 4); CPCOM();

        const uint32_t* Kb = smw + OFF_K + (ct % 3) * TILE_W;

        // S = Q K^T  (warp cols: wc*16 .. wc*16+15)
        float S[2][4];
        #pragma unroll
        for (int ni = 0; ni < 2; ++ni)
            #pragma unroll
            for (int e = 0; e < 4; ++e) S[ni][e] = 0.0f;
        #pragma unroll
        for (int kk = 0; kk < 4; ++kk) {
            uint32_t a[4], b[2];
            const uint32_t* qp = Qw + rowa * KSTR + kk * 8 + four;
            a[0] = qp[0]; a[1] = qp[8 * KSTR]; a[2] = qp[4]; a[3] = qp[8 * KSTR + 4];
            #pragma unroll
            for (int ni = 0; ni < 2; ++ni) {
                const uint32_t* kp = Kb + (wc * 16 + ni * 8 + qr) * KSTR + kk * 8 + four;
                b[0] = kp[0]; b[1] = kp[4];
                mma_bf16(S[ni], a, b);
            }
        }

        // deferred PV_{ct-1}
        if (ct > 0) {
            const uint32_t* Pp = smw + OFF_P + ((ct - 1) & 1) * TILE_W;
            const uint32_t* Mb = smw + OFF_M + ((ct - 1) % 4) * TILE_W;
            #pragma unroll
            for (int kk = 0; kk < 4; ++kk) {
                uint32_t a[4], b[2];
                const uint32_t* pp = Pp + rowa * KSTR + kk * 8 + four;
                a[0] = pp[0]; a[1] = pp[8 * KSTR]; a[2] = pp[4]; a[3] = pp[8 * KSTR + 4];
                #pragma unroll
                for (int ni = 0; ni < 2; ++ni) {
                    const uint32_t* mp = Mb + (wc * 16 + ni * 8 + qr) * KSTR + kk * 8 + four;
                    b[0] = mp[0]; b[1] = mp[4];
                    mma_bf16(acc[ni], a, b);
                }
            }
        }

        // p = adj ? exp2(s + sr*sc*sbc) : 0  -> P buf ct%2
        uint32_t* Pw = smw + OFF_P + (ct & 1) * TILE_W;
        #pragma unroll
        for (int ni = 0; ni < 2; ++ni) {
            float2 a0 = adjv[ni*2+0], a1 = adjv[ni*2+1], sc2 = scv[ni];
            float p00 = (a0.x == 0.0f) ? 0.0f : ex2f(fmaf(srb0, sc2.x, S[ni][0]));
            float p01 = (a0.y == 0.0f) ? 0.0f : ex2f(fmaf(srb0, sc2.y, S[ni][1]));
            float p10 = (a1.x == 0.0f) ? 0.0f : ex2f(fmaf(srb1, sc2.x, S[ni][2]));
            float p11 = (a1.y == 0.0f) ? 0.0f : ex2f(fmaf(srb1, sc2.y, S[ni][3]));
            psum0 += p00 + p01;
            psum1 += p10 + p11;
            int cw = wc * 8 + ni * 4 + four;
            Pw[rowa * KSTR + cw]       = pkbf(p00, p01);
            Pw[(rowa + 8) * KSTR + cw] = pkbf(p10, p11);
        }
    }
    CPWAIT(0);
    __syncthreads();

    // trailing PV_127
    {
        const uint32_t* Pp = smw + OFF_P + (127 & 1) * TILE_W;
        const uint32_t* Mb = smw + OFF_M + (127 % 4) * TILE_W;
        #pragma unroll
        for (int kk = 0; kk < 4; ++kk) {
            uint32_t a[4], b[2];
            const uint32_t* pp = Pp + rowa * KSTR + kk * 8 + four;
            a[0] = pp[0]; a[1] = pp[8 * KSTR]; a[2] = pp[4]; a[3] = pp[8 * KSTR + 4];
            #pragma unroll
            for (int ni = 0; ni < 2; ++ni) {
                const uint32_t* mp = Mb + (wc * 16 + ni * 8 + qr) * KSTR + kk * 8 + four;
                b[0] = mp[0]; b[1] = mp[4];
                mma_bf16(acc[ni], a, b);
            }
        }
    }

    // l reduction: 4 wc-partials per row
    psum0 += __shfl_xor_sync(0xffffffffu, psum0, 1);
    psum0 += __shfl_xor_sync(0xffffffffu, psum0, 2);
    psum1 += __shfl_xor_sync(0xffffffffu, psum1, 1);
    psum1 += __shfl_xor_sync(0xffffffffu, psum1, 2);
    if (four == 0) {
        redl[wc * 64 + rowa]     = psum0;
        redl[wc * 64 + rowa + 8] = psum1;
    }
    __syncthreads();
    float inv0 = 1.0f / (redl[rowa] + redl[64 + rowa] + redl[128 + rowa] + redl[192 + rowa]);
    float inv1 = 1.0f / (redl[rowa + 8] + redl[64 + rowa + 8] + redl[128 + rowa + 8] + redl[192 + rowa + 8]);

    // z = h + O/l -> zbuf, layernorm
    float* zbuf = (float*)smw;   // 64 x stride 66 < OFF_M
    #pragma unroll
    for (int ni = 0; ni < 2; ++ni) {
        int col = wc * 16 + ni * 8 + 2 * four;
        float2 h0 = *(const float2*)(g_h + (size_t)(r0 + rowa) * 64 + col);
        float2 h1 = *(const float2*)(g_h + (size_t)(r0 + rowa + 8) * 64 + col);
        float2 z0, z1;
        z0.x = h0.x + acc[ni][0] * inv0;  z0.y = h0.y + acc[ni][1] * inv0;
        z1.x = h1.x + acc[ni][2] * inv1;  z1.y = h1.y + acc[ni][3] * inv1;
        *(float2*)(zbuf + rowa * 66 + col)       = z0;
        *(float2*)(zbuf + (rowa + 8) * 66 + col) = z1;
    }
    __syncthreads();
    if (t < 64) {
        float sum = 0.0f;
        #pragma unroll 16
        for (int c = 0; c < 64; ++c) sum += zbuf[t * 66 + c];
        float mu = sum * (1.0f / 64.0f);
        float sq = 0.0f;
        #pragma unroll 16
        for (int c = 0; c < 64; ++c) { float dz = zbuf[t * 66 + c] - mu; sq += dz * dz; }
        float rstd = rsqrtf(sq * (1.0f / 64.0f) + 1e-5f);
        #pragma unroll 16
        for (int c = 0; c < 64; ++c)
            g_emb[(size_t)(r0 + t) * 64 + c] = (zbuf[t * 66 + c] - mu) * rstd * lng[c] + lnb[c];
    }
}

// ---------------- Kernel 3: DQN head — warp per node, 64 nodes/block ------------
__global__ void __launch_bounds__(256) k_head(
    const float* __restrict__ sa, const float* __restrict__ wa1,
    const float* __restrict__ ba1, const float* __restrict__ wa2,
    const float* __restrict__ ba2, float* __restrict__ out) {
    __shared__ float swa1[66*64];
    __shared__ float swa2[64*3];
    int t = threadIdx.x;
    for (int idx = t; idx < 66*64; idx += 256) swa1[idx] = wa1[idx];
    if (t < 192) swa2[t] = wa2[t];
    __syncthreads();
    int warp = t >> 5, lane = t & 31;
    float b0 = ba1[2*lane], b1 = ba1[2*lane+1];
    for (int it = 0; it < 8; ++it) {
        int i = blockIdx.x * 64 + it * 8 + warp;
        float2 e = *(const float2*)(g_emb + (size_t)i * 64 + 2 * lane);
        float2 s2 = *(const float2*)(sa + i * 2);
        float acc0a = b0, acc1a = b1, acc0b = 0.0f, acc1b = 0.0f;
        #pragma unroll
        for (int ee = 0; ee < 32; ++ee) {
            float va = __shfl_sync(0xffffffffu, (ee & 1) ? e.y : e.x, ee >> 1);
            float vb = __shfl_sync(0xffffffffu, (ee & 1) ? e.y : e.x, (ee + 32) >> 1);
            float2 wa = *(const float2*)(swa1 + ee * 64 + 2 * lane);
            float2 wb = *(const float2*)(swa1 + (ee + 32) * 64 + 2 * lane);
            acc0a += va * wa.x; acc1a += va * wa.y;
            acc0b += vb * wb.x; acc1b += vb * wb.y;
        }
        { float2 w = *(const float2*)(swa1 + 64*64 + 2*lane); acc0a += s2.x * w.x; acc1a += s2.x * w.y; }
        { float2 w = *(const float2*)(swa1 + 65*64 + 2*lane); acc0b += s2.y * w.x; acc1b += s2.y * w.y; }
        float acc0 = fmaxf(acc0a + acc0b, 0.0f);
        float acc1 = fmaxf(acc1a + acc1b, 0.0f);
        float o0 = acc0 * swa2[(2*lane)*3+0] + acc1 * swa2[(2*lane+1)*3+0];
        float o1 = acc0 * swa2[(2*lane)*3+1] + acc1 * swa2[(2*lane+1)*3+1];
        float o2 = acc0 * swa2[(2*lane)*3+2] + acc1 * swa2[(2*lane+1)*3+2];
        #pragma unroll
        for (int off = 16; off > 0; off >>= 1) {
            o0 += __shfl_xor_sync(0xffffffffu, o0, off);
            o1 += __shfl_xor_sync(0xffffffffu, o1, off);
            o2 += __shfl_xor_sync(0xffffffffu, o2, off);
        }
        if (lane == 0) {
            out[i*3+0] = o0 + ba2[0];
            out[i*3+1] = o1 + ba2[1];
            out[i*3+2] = o2 + ba2[2];
        }
    }
}

extern "C" void kernel_launch(void* const* d_in, const int* in_sizes, int n_in,
                              void* d_out, int out_size) {
    const float* nf    = (const float*)d_in[0];
    const float* adj   = (const float*)d_in[1];
    const float* trig  = (const float*)d_in[2];
    const float* sa    = (const float*)d_in[3];
    const float* w1    = (const float*)d_in[4];
    const float* b1    = (const float*)d_in[5];
    const float* w2    = (const float*)d_in[6];
    const float* b2    = (const float*)d_in[7];
    const float* wq    = (const float*)d_in[8];
    const float* bq    = (const float*)d_in[9];
    const float* wk    = (const float*)d_in[10];
    const float* bk    = (const float*)d_in[11];
    const float* wg    = (const float*)d_in[12];
    const float* bg    = (const float*)d_in[13];
    const float* sbias = (const float*)d_in[14];
    const float* wm    = (const float*)d_in[15];
    const float* bm    = (const float*)d_in[16];
    const float* lng   = (const float*)d_in[17];
    const float* lnb   = (const float*)d_in[18];
    const float* wa1   = (const float*)d_in[19];
    const float* ba1   = (const float*)d_in[20];
    const float* wa2   = (const float*)d_in[21];
    const float* ba2   = (const float*)d_in[22];
    float* out = (float*)d_out;

    const int smem = SMEM_WORDS * 4;  // 93,184 B
    cudaFuncSetAttribute(k_attn, cudaFuncAttributeMaxDynamicSharedMemorySize, smem);

    k_scalars<<<1, 64>>>(trig, wg, bg, sbias);
    k_mlp<<<256, 256>>>(nf, trig, w1, b1, w2, b2, wq, bq, wk, bk, wm, bm);
    k_attn<<<128, 512, smem>>>(adj, lng, lnb);
    k_head<<<128, 256>>>(sa, wa1, ba1, wa2, ba2, out);
}

// round 11
// speedup vs baseline: 1.2460x; 1.2460x over previous
#include <cuda_runtime.h>
#include <cuda_bf16.h>
#include <math_constants.h>
#include <cstdint>

#define NN 8192
#define L2E 1.4426950408889634f

__device__ float g_h[NN*64];
__device__ __nv_bfloat16 g_q[NN*64];   // pre-scaled by gate * 0.125 * log2(e)
__device__ __nv_bfloat16 g_k[NN*64];
__device__ __nv_bfloat16 g_mT[64*NN];  // transposed: [dim][node]
__device__ float g_pO[2*NN*64];        // partial (unnormalized) O per column half
__device__ float g_pl[2*NN];           // partial l per column half
__device__ float g_s[NN];
__device__ float g_gate;
__device__ float g_sbc;                // stateful_bias * (1 - t0) * log2(e)

__device__ __forceinline__ float ex2f(float x) {
    float y; asm("ex2.approx.ftz.f32 %0, %1;" : "=f"(y) : "f"(x)); return y;
}
__device__ __forceinline__ uint32_t pkbf(float a, float b) {
    __nv_bfloat162 t = __floats2bfloat162_rn(a, b);
    return *reinterpret_cast<uint32_t*>(&t);
}
__device__ __forceinline__ void mma_bf16(float* c, const uint32_t* a, const uint32_t* b) {
    asm volatile("mma.sync.aligned.m16n8k16.row.col.f32.bf16.bf16.f32 "
                 "{%0,%1,%2,%3},{%4,%5,%6,%7},{%8,%9},{%0,%1,%2,%3};"
                 : "+f"(c[0]), "+f"(c[1]), "+f"(c[2]), "+f"(c[3])
                 : "r"(a[0]), "r"(a[1]), "r"(a[2]), "r"(a[3]), "r"(b[0]), "r"(b[1]));
}
#define CP16(d, s) asm volatile("cp.async.cg.shared.global [%0], [%1], 16;" :: "r"(d), "l"(s))
#define CPCOM()    asm volatile("cp.async.commit_group;" ::: "memory")
#define CPWAIT(n)  asm volatile("cp.async.wait_group %0;" :: "n"(n) : "memory")

// ---------------- Kernel 0: scalars ---------------------------------------------
__global__ void k_scalars(const float* __restrict__ trig, const float* __restrict__ wg,
                          const float* __restrict__ bg, const float* __restrict__ sbias) {
    int d = threadIdx.x;
    float t0 = trig[0], t1 = trig[1];
    float v = t0 * wg[d] + t1 * wg[64 + d] + bg[d];
    float sig = 1.0f / (1.0f + __expf(-v));
    #pragma unroll
    for (int o = 16; o > 0; o >>= 1) sig += __shfl_xor_sync(0xffffffffu, sig, o);
    __shared__ float ws[2];
    if ((d & 31) == 0) ws[d >> 5] = sig;
    __syncthreads();
    if (d == 0) {
        g_gate = (ws[0] + ws[1]) * (1.0f / 64.0f);
        g_sbc  = sbias[0] * (1.0f - t0) * L2E;
    }
}

// ---------------- Kernel 1: per-node MLP, 8-node register blocking --------------
// 256 threads = 4 groups x 64 dims; each group owns 8 nodes; weights read ONCE.
__global__ void __launch_bounds__(256) k_mlp(
    const float* __restrict__ nf, const float* __restrict__ trig,
    const float* __restrict__ w1, const float* __restrict__ b1,
    const float* __restrict__ w2, const float* __restrict__ b2,
    const float* __restrict__ wq, const float* __restrict__ bq,
    const float* __restrict__ wk, const float* __restrict__ bk,
    const float* __restrict__ wm, const float* __restrict__ bm) {
    __shared__ float h1[4][8][64];
    __shared__ float hh[4][8][64];
    __shared__ float stg[64][36];
    int g = threadIdx.x >> 6, d = threadIdx.x & 63;
    float t0 = trig[0], t1 = trig[1];
    float qsc = g_gate * 0.125f * L2E;
    int i0 = blockIdx.x * 32;
    int nb = i0 + g * 8;

    // phase 1: h1 = relu(x @ w1 + b1)
    float w10 = w1[d], w11 = w1[64+d], w12 = w1[128+d], w13 = w1[192+d], w14 = w1[256+d];
    float b1v = b1[d];
    #pragma unroll
    for (int n = 0; n < 8; ++n) {
        int i = nb + n;
        float x0 = nf[i*3+0], x1 = nf[i*3+1], x2 = nf[i*3+2];
        float a = b1v + x0*w10 + x1*w11 + x2*w12 + t0*w13 + t1*w14;
        h1[g][n][d] = fmaxf(a, 0.0f);
        if (d == 0) g_s[i] = x2;
    }
    __syncthreads();

    // phase 2: h = h1 @ w2 + b2   (w2 element read once per thread)
    float s2[8];
    float b2v = b2[d];
    #pragma unroll
    for (int n = 0; n < 8; ++n) s2[n] = b2v;
    for (int e = 0; e < 64; ++e) {
        float w = w2[e*64 + d];
        #pragma unroll
        for (int n = 0; n < 8; ++n) s2[n] += h1[g][n][e] * w;
    }
    #pragma unroll
    for (int n = 0; n < 8; ++n) { hh[g][n][d] = s2[n]; g_h[(size_t)(nb+n)*64 + d] = s2[n]; }
    __syncthreads();

    // phase 3: q, k, m = h @ {wq,wk,wm} + bias  (each weight element read once)
    float qa[8], ka[8], ma[8];
    float bqv = bq[d], bkv = bk[d], bmv = bm[d];
    #pragma unroll
    for (int n = 0; n < 8; ++n) { qa[n] = bqv; ka[n] = bkv; ma[n] = bmv; }
    for (int e = 0; e < 64; ++e) {
        float wqv = wq[e*64 + d], wkv = wk[e*64 + d], wmv = wm[e*64 + d];
        #pragma unroll
        for (int n = 0; n < 8; ++n) {
            float he = hh[g][n][e];
            qa[n] += he * wqv; ka[n] += he * wkv; ma[n] += he * wmv;
        }
    }
    #pragma unroll
    for (int n = 0; n < 8; ++n) {
        g_q[(size_t)(nb+n)*64 + d] = __float2bfloat16(qa[n] * qsc);
        g_k[(size_t)(nb+n)*64 + d] = __float2bfloat16(ka[n]);
        stg[d][g*8 + n] = ma[n];
    }
    __syncthreads();
    // transposed write-out of m
    int dd = threadIdx.x >> 2, p = threadIdx.x & 3;
    float4 v0 = *(float4*)&stg[dd][p*8];
    float4 v1 = *(float4*)&stg[dd][p*8 + 4];
    uint32_t o[4] = {pkbf(v0.x, v0.y), pkbf(v0.z, v0.w), pkbf(v1.x, v1.y), pkbf(v1.z, v1.w)};
    *(uint4*)(g_mT + (size_t)dd*NN + i0 + p*8) = *(uint4*)o;
}

// ---------------- Kernel 2: flash attention, column-split, pipelined PV ---------
// grid 256 = 128 row-tiles x 2 column halves; 8 warps (4x2); warp tile 16x32.
// K: 3 bufs, M: 4 bufs, P: 2 bufs (PV deferred one iteration).
#define KSTR 36
#define TILE_W (64*KSTR)          // 2304 words
#define OFF_K 0                   // 3 tiles
#define OFF_M (3*TILE_W)          // 4 tiles
#define OFF_Q (7*TILE_W)
#define OFF_P (8*TILE_W)          // 2 tiles
#define OFF_RED (10*TILE_W)       // 2x64 words
#define SMEM_WORDS (10*TILE_W + 128)

__global__ void __launch_bounds__(256) k_attn(const float* __restrict__ adj) {
    extern __shared__ uint32_t smw[];
    const int t = threadIdx.x;
    const int warp = t >> 5, lane = t & 31;
    const int wr = warp >> 1, wc = warp & 1;
    const int qr = lane >> 2, four = lane & 3;
    const int rt = blockIdx.x >> 1, half = blockIdx.x & 1;
    const int r0 = rt * 64;
    const int cb0 = half * 4096;
    const int rowa = wr * 16 + qr;
    const uint32_t sbase = (uint32_t)__cvta_generic_to_shared(smw);

    auto cpK = [&](int ct2, int buf) {   // ct2 = local tile index within half
        uint32_t dk = sbase + (OFF_K + buf * TILE_W) * 4;
        #pragma unroll
        for (int rep = 0; rep < 2; ++rep) {
            int idx = t + rep * 256;
            int r = idx >> 3, c = idx & 7;
            CP16(dk + (r * KSTR + c * 4) * 4, g_k + (size_t)(cb0 + ct2 * 64 + r) * 64 + c * 8);
        }
    };
    auto cpM = [&](int ct2, int buf) {
        uint32_t dm = sbase + (OFF_M + buf * TILE_W) * 4;
        #pragma unroll
        for (int rep = 0; rep < 2; ++rep) {
            int idx = t + rep * 256;
            int r = idx >> 3, c = idx & 7;
            CP16(dm + (r * KSTR + c * 4) * 4, g_mT + (size_t)r * NN + cb0 + ct2 * 64 + c * 8);
        }
    };
    // prologue: Q + tiles 0,1
    {
        uint32_t dq = sbase + OFF_Q * 4;
        #pragma unroll
        for (int rep = 0; rep < 2; ++rep) {
            int idx = t + rep * 256;
            int r = idx >> 3, c = idx & 7;
            CP16(dq + (r * KSTR + c * 4) * 4, g_q + (size_t)(r0 + r) * 64 + c * 8);
        }
        cpK(0, 0); cpM(0, 0); CPCOM();
        cpK(1, 1); cpM(1, 1); CPCOM();
    }

    const float sbc = g_sbc;
    const float srb0 = g_s[r0 + rowa] * sbc;
    const float srb1 = g_s[r0 + rowa + 8] * sbc;
    const float* adjr0 = adj + (size_t)(r0 + rowa) * NN + cb0 + wc * 32 + 2 * four;
    const float* adjr1 = adjr0 + (size_t)8 * NN;

    const uint32_t* Qw = smw + OFF_Q;
    float* redl = (float*)(smw + OFF_RED);

    float psum0 = 0.0f, psum1 = 0.0f;
    float acc[4][4];
    #pragma unroll
    for (int ni = 0; ni < 4; ++ni)
        #pragma unroll
        for (int e = 0; e < 4; ++e) acc[ni][e] = 0.0f;

    for (int ct = 0; ct < 64; ++ct) {
        const int c0 = ct * 64;   // offset within the half
        float2 adjv[8], scv[4];
        #pragma unroll
        for (int ni = 0; ni < 4; ++ni) {
            scv[ni]      = *(const float2*)(g_s + cb0 + c0 + wc * 32 + ni * 8 + 2 * four);
            adjv[ni*2+0] = __ldcs((const float2*)(adjr0 + c0 + ni * 8));
            adjv[ni*2+1] = __ldcs((const float2*)(adjr1 + c0 + ni * 8));
        }
        CPWAIT(1);
        __syncthreads();   // tile ct visible; P_{ct-1} stores visible; prev bufs free
        int nt = ct + 2; if (nt > 63) nt = 63;
        cpK(nt, (ct + 2) % 3); cpM(nt, (ct + 2) % 4); CPCOM();

        const uint32_t* Kb = smw + OFF_K + (ct % 3) * TILE_W;

        // S = Q K^T
        float S[4][4];
        #pragma unroll
        for (int ni = 0; ni < 4; ++ni)
            #pragma unroll
            for (int e = 0; e < 4; ++e) S[ni][e] = 0.0f;
        #pragma unroll
        for (int kk = 0; kk < 4; ++kk) {
            uint32_t a[4], b[2];
            const uint32_t* qp = Qw + rowa * KSTR + kk * 8 + four;
            a[0] = qp[0]; a[1] = qp[8 * KSTR]; a[2] = qp[4]; a[3] = qp[8 * KSTR + 4];
            #pragma unroll
            for (int ni = 0; ni < 4; ++ni) {
                const uint32_t* kp = Kb + (wc * 32 + ni * 8 + qr) * KSTR + kk * 8 + four;
                b[0] = kp[0]; b[1] = kp[4];
                mma_bf16(S[ni], a, b);
            }
        }

        // deferred PV_{ct-1}
        if (ct > 0) {
            const uint32_t* Pp = smw + OFF_P + ((ct - 1) & 1) * TILE_W;
            const uint32_t* Mb = smw + OFF_M + ((ct - 1) % 4) * TILE_W;
            #pragma unroll
            for (int kk = 0; kk < 4; ++kk) {
                uint32_t a[4], b[2];
                const uint32_t* pp = Pp + rowa * KSTR + kk * 8 + four;
                a[0] = pp[0]; a[1] = pp[8 * KSTR]; a[2] = pp[4]; a[3] = pp[8 * KSTR + 4];
                #pragma unroll
                for (int ni = 0; ni < 4; ++ni) {
                    const uint32_t* mp = Mb + (wc * 32 + ni * 8 + qr) * KSTR + kk * 8 + four;
                    b[0] = mp[0]; b[1] = mp[4];
                    mma_bf16(acc[ni], a, b);
                }
            }
        }

        // p = adj ? exp2(s + sr*sc*sbc) : 0  -> P buf ct%2
        uint32_t* Pw = smw + OFF_P + (ct & 1) * TILE_W;
        #pragma unroll
        for (int ni = 0; ni < 4; ++ni) {
            float2 a0 = adjv[ni*2+0], a1 = adjv[ni*2+1], sc2 = scv[ni];
            float p00 = (a0.x == 0.0f) ? 0.0f : ex2f(fmaf(srb0, sc2.x, S[ni][0]));
            float p01 = (a0.y == 0.0f) ? 0.0f : ex2f(fmaf(srb0, sc2.y, S[ni][1]));
            float p10 = (a1.x == 0.0f) ? 0.0f : ex2f(fmaf(srb1, sc2.x, S[ni][2]));
            float p11 = (a1.y == 0.0f) ? 0.0f : ex2f(fmaf(srb1, sc2.y, S[ni][3]));
            psum0 += p00 + p01;
            psum1 += p10 + p11;
            int cw = wc * 16 + ni * 4 + four;
            Pw[rowa * KSTR + cw]       = pkbf(p00, p01);
            Pw[(rowa + 8) * KSTR + cw] = pkbf(p10, p11);
        }
    }
    CPWAIT(0);
    __syncthreads();

    // trailing PV_63
    {
        const uint32_t* Pp = smw + OFF_P + (63 & 1) * TILE_W;
        const uint32_t* Mb = smw + OFF_M + (63 % 4) * TILE_W;
        #pragma unroll
        for (int kk = 0; kk < 4; ++kk) {
            uint32_t a[4], b[2];
            const uint32_t* pp = Pp + rowa * KSTR + kk * 8 + four;
            a[0] = pp[0]; a[1] = pp[8 * KSTR]; a[2] = pp[4]; a[3] = pp[8 * KSTR + 4];
            #pragma unroll
            for (int ni = 0; ni < 4; ++ni) {
                const uint32_t* mp = Mb + (wc * 32 + ni * 8 + qr) * KSTR + kk * 8 + four;
                b[0] = mp[0]; b[1] = mp[4];
                mma_bf16(acc[ni], a, b);
            }
        }
    }

    // partial l
    psum0 += __shfl_xor_sync(0xffffffffu, psum0, 1);
    psum0 += __shfl_xor_sync(0xffffffffu, psum0, 2);
    psum1 += __shfl_xor_sync(0xffffffffu, psum1, 1);
    psum1 += __shfl_xor_sync(0xffffffffu, psum1, 2);
    if (four == 0) {
        redl[wc * 64 + rowa]     = psum0;
        redl[wc * 64 + rowa + 8] = psum1;
    }
    __syncthreads();
    if (t < 64) g_pl[(size_t)half * NN + r0 + t] = redl[t] + redl[64 + t];

    // partial (unnormalized) O
    float* op = g_pO + (size_t)half * NN * 64;
    #pragma unroll
    for (int ni = 0; ni < 4; ++ni) {
        int col = wc * 32 + ni * 8 + 2 * four;
        float2 z0, z1;
        z0.x = acc[ni][0]; z0.y = acc[ni][1];
        z1.x = acc[ni][2]; z1.y = acc[ni][3];
        *(float2*)(op + (size_t)(r0 + rowa) * 64 + col)     = z0;
        *(float2*)(op + (size_t)(r0 + rowa + 8) * 64 + col) = z1;
    }
}

// ---------------- Kernel 3: combine halves + layernorm + DQN head ---------------
__global__ void __launch_bounds__(256) k_head(
    const float* __restrict__ sa, const float* __restrict__ wa1,
    const float* __restrict__ ba1, const float* __restrict__ wa2,
    const float* __restrict__ ba2, const float* __restrict__ lng,
    const float* __restrict__ lnb, float* __restrict__ out) {
    __shared__ float swa1[66*64];
    __shared__ float swa2[64*3];
    int t = threadIdx.x;
    for (int idx = t; idx < 66*64; idx += 256) swa1[idx] = wa1[idx];
    if (t < 192) swa2[t] = wa2[t];
    __syncthreads();
    int warp = t >> 5, lane = t & 31;
    float b0 = ba1[2*lane], b1 = ba1[2*lane+1];
    float2 lg = *(const float2*)(lng + 2*lane);
    float2 lb = *(const float2*)(lnb + 2*lane);
    for (int it = 0; it < 4; ++it) {
        int i = blockIdx.x * 32 + it * 8 + warp;
        float2 h2 = *(const float2*)(g_h + (size_t)i * 64 + 2 * lane);
        float2 o0 = *(const float2*)(g_pO + (size_t)i * 64 + 2 * lane);
        float2 o1 = *(const float2*)(g_pO + (size_t)(NN + i) * 64 + 2 * lane);
        float linv = 1.0f / (g_pl[i] + g_pl[NN + i]);
        float zx = h2.x + (o0.x + o1.x) * linv;
        float zy = h2.y + (o0.y + o1.y) * linv;
        float s = zx + zy;
        #pragma unroll
        for (int o = 16; o > 0; o >>= 1) s += __shfl_xor_sync(0xffffffffu, s, o);
        float mu = s * (1.0f / 64.0f);
        float d0 = zx - mu, d1 = zy - mu;
        float q = d0 * d0 + d1 * d1;
        #pragma unroll
        for (int o = 16; o > 0; o >>= 1) q += __shfl_xor_sync(0xffffffffu, q, o);
        float rstd = rsqrtf(q * (1.0f / 64.0f) + 1e-5f);
        float ex = d0 * rstd * lg.x + lb.x;
        float ey = d1 * rstd * lg.y + lb.y;
        float2 s2 = *(const float2*)(sa + i * 2);
        float acc0a = b0, acc1a = b1, acc0b = 0.0f, acc1b = 0.0f;
        #pragma unroll
        for (int ee = 0; ee < 32; ++ee) {
            float va = __shfl_sync(0xffffffffu, (ee & 1) ? ey : ex, ee >> 1);
            float vb = __shfl_sync(0xffffffffu, (ee & 1) ? ey : ex, (ee + 32) >> 1);
            float2 wa = *(const float2*)(swa1 + ee * 64 + 2 * lane);
            float2 wb = *(const float2*)(swa1 + (ee + 32) * 64 + 2 * lane);
            acc0a += va * wa.x; acc1a += va * wa.y;
            acc0b += vb * wb.x; acc1b += vb * wb.y;
        }
        { float2 w = *(const float2*)(swa1 + 64*64 + 2*lane); acc0a += s2.x * w.x; acc1a += s2.x * w.y; }
        { float2 w = *(const float2*)(swa1 + 65*64 + 2*lane); acc0b += s2.y * w.x; acc1b += s2.y * w.y; }
        float acc0 = fmaxf(acc0a + acc0b, 0.0f);
        float acc1 = fmaxf(acc1a + acc1b, 0.0f);
        float o0v = acc0 * swa2[(2*lane)*3+0] + acc1 * swa2[(2*lane+1)*3+0];
        float o1v = acc0 * swa2[(2*lane)*3+1] + acc1 * swa2[(2*lane+1)*3+1];
        float o2v = acc0 * swa2[(2*lane)*3+2] + acc1 * swa2[(2*lane+1)*3+2];
        #pragma unroll
        for (int off = 16; off > 0; off >>= 1) {
            o0v += __shfl_xor_sync(0xffffffffu, o0v, off);
            o1v += __shfl_xor_sync(0xffffffffu, o1v, off);
            o2v += __shfl_xor_sync(0xffffffffu, o2v, off);
        }
        if (lane == 0) {
            out[i*3+0] = o0v + ba2[0];
            out[i*3+1] = o1v + ba2[1];
            out[i*3+2] = o2v + ba2[2];
        }
    }
}

extern "C" void kernel_launch(void* const* d_in, const int* in_sizes, int n_in,
                              void* d_out, int out_size) {
    const float* nf    = (const float*)d_in[0];
    const float* adj   = (const float*)d_in[1];
    const float* trig  = (const float*)d_in[2];
    const float* sa    = (const float*)d_in[3];
    const float* w1    = (const float*)d_in[4];
    const float* b1    = (const float*)d_in[5];
    const float* w2    = (const float*)d_in[6];
    const float* b2    = (const float*)d_in[7];
    const float* wq    = (const float*)d_in[8];
    const float* bq    = (const float*)d_in[9];
    const float* wk    = (const float*)d_in[10];
    const float* bk    = (const float*)d_in[11];
    const float* wg    = (const float*)d_in[12];
    const float* bg    = (const float*)d_in[13];
    const float* sbias = (const float*)d_in[14];
    const float* wm    = (const float*)d_in[15];
    const float* bm    = (const float*)d_in[16];
    const float* lng   = (const float*)d_in[17];
    const float* lnb   = (const float*)d_in[18];
    const float* wa1   = (const float*)d_in[19];
    const float* ba1   = (const float*)d_in[20];
    const float* wa2   = (const float*)d_in[21];
    const float* ba2   = (const float*)d_in[22];
    float* out = (float*)d_out;

    const int smem = SMEM_WORDS * 4;  // 92,672 B
    cudaFuncSetAttribute(k_attn, cudaFuncAttributeMaxDynamicSharedMemorySize, smem);

    k_scalars<<<1, 64>>>(trig, wg, bg, sbias);
    k_mlp<<<256, 256>>>(nf, trig, w1, b1, w2, b2, wq, bq, wk, bk, wm, bm);
    k_attn<<<256, 256, smem>>>(adj);
    k_head<<<256, 256>>>(sa, wa1, ba1, wa2, ba2, lng, lnb, out);
}